// round 15
// baseline (speedup 1.0000x reference)
#include <cuda_runtime.h>
#include <cstdint>

namespace {
constexpr int L2C   = 65536;
constexpr int NC    = 2 * L2C;      // 131072
constexpr int FINC  = 8;
constexpr int FOUTC = 8;
constexpr int KC    = 13;
constexpr int IK    = FINC * KC;    // 104
constexpr int EPB   = 32;           // edges per block
constexpr int TPB   = 256;          // 8 warps
constexpr int CHE   = 4;            // edges per chunk
constexpr int NCH   = EPB / CHE;    // 8 chunks
constexpr int WPE   = IK * FOUTC;   // 832 mask elements per edge
constexpr int HWRD  = WPE / 2;      // 416 words per (edge, o-half) warp slice
constexpr int SLICE_B = HWRD * 4;   // 1664 B per warp slice (word mode)
constexpr int STAGE_B = 8 * SLICE_B;// 13312 B per ring stage (8 warps)
}

// x transposed to (N, FIN): one gathered column = one 32B sector.
__device__ __align__(16) float g_xt[(size_t)NC * FINC];
// 0 => 4-byte mask words ({0,1} int32 or {0,1.0f} float32); 1 => 1-byte elements
__device__ int g_mask_is_byte;

__global__ __launch_bounds__(TPB) void prep_kernel(const float* __restrict__ x,
                                                   const uint32_t* __restrict__ M) {
    if (blockIdx.x == 0 && threadIdx.x < 32) {
        int bad = 0;
        #pragma unroll
        for (int r = 0; r < 8; r++) {
            uint32_t w = M[r * 32 + threadIdx.x];
            if (!(w == 0u || w == 1u || w == 0x3f800000u)) bad = 1;
        }
        bad = __any_sync(0xffffffffu, bad);
        if (threadIdx.x == 0) g_mask_is_byte = bad;
    }
    int j = blockIdx.x * blockDim.x + threadIdx.x;
    if (j >= NC) return;
    float4 a, b;
    a.x = x[0 * NC + j]; a.y = x[1 * NC + j]; a.z = x[2 * NC + j]; a.w = x[3 * NC + j];
    b.x = x[4 * NC + j]; b.y = x[5 * NC + j]; b.z = x[6 * NC + j]; b.w = x[7 * NC + j];
    float4* dst = reinterpret_cast<float4*>(g_xt) + (size_t)j * 2;
    dst[0] = a;
    dst[1] = b;
}

// ---- cache-policy + cp.async helpers ----
__device__ __forceinline__ uint64_t pol_evict_first() {
    uint64_t p;
    asm("createpolicy.fractional.L2::evict_first.b64 %0, 1.0;" : "=l"(p));
    return p;
}
__device__ __forceinline__ uint64_t pol_evict_last() {
    uint64_t p;
    asm("createpolicy.fractional.L2::evict_last.b64 %0, 1.0;" : "=l"(p));
    return p;
}
__device__ __forceinline__ void cp16_stream(uint32_t dst_smem, const void* src, uint64_t pol) {
    asm volatile("cp.async.cg.shared.global.L2::cache_hint [%0], [%1], 16, %2;"
                 :: "r"(dst_smem), "l"(src), "l"(pol) : "memory");
}
__device__ __forceinline__ void cp_commit() {
    asm volatile("cp.async.commit_group;" ::: "memory");
}
template <int N> __device__ __forceinline__ void cp_wait() {
    asm volatile("cp.async.wait_group %0;" :: "n"(N) : "memory");
}
__device__ __forceinline__ float ld_pin(const float* p, uint64_t pol) {
    float v;
    asm volatile("ld.global.nc.L2::cache_hint.f32 %0, [%1], %2;"
                 : "=f"(v) : "l"(p), "l"(pol));
    return v;
}

__global__ __launch_bounds__(TPB, 5) void edge_kernel(
    const float* __restrict__ Wh, const float* __restrict__ Wv,
    const float* __restrict__ bh, const float* __restrict__ bv,
    const uint8_t* __restrict__ Mh, const uint8_t* __restrict__ Mv,
    const int* __restrict__ Kh, const int* __restrict__ Kv,
    const int* __restrict__ ELh, const int* __restrict__ ELv,
    float* __restrict__ out)
{
    const bool vert = (blockIdx.y != 0);
    const float*   W    = vert ? Wv  : Wh;
    const float*   bias = vert ? bv  : bh;
    const uint8_t* M    = vert ? Mv  : Mh;
    const int*     KER  = vert ? Kv  : Kh;
    const int*     EL   = vert ? ELv : ELh;

    __shared__ __align__(16) uint32_t mbuf[2 * STAGE_B / 4];  // 26624 B, warp-sliced ring
    __shared__ __align__(16) float    xsf[EPB * IK];          // 13312 B
    __shared__ int   kers[EPB * KC];
    __shared__ int   els[EPB];
    __shared__ float bsh[FOUTC];

    const int tid  = threadIdx.x;
    const int lane = tid & 31;
    const int w    = tid >> 5;          // warp 0..7
    const int e0   = blockIdx.x * EPB;

    const uint64_t polF = pol_evict_first();
    const uint64_t polL = pol_evict_last();

    // ---- small tables ----
    for (int t = tid; t < EPB * KC; t += TPB) kers[t] = KER[e0 * KC + t];
    if (tid < EPB)   els[tid] = EL[e0 + tid];
    if (tid < FOUTC) bsh[tid] = bias[tid];

    // ---- warp roles: cel = w>>1 (edge slot in chunk), half = w&1 (o-half) ----
    const int celw = w >> 1;
    const int half = w & 1;
    const int ii   = lane & 7;
    const int o    = half * 4 + (lane >> 3);
    const int lp   = half * 32 + lane;        // o*8 + ii

    // W row (o, ii): 13 registers (L2-resident)
    float wreg[KC];
    #pragma unroll
    for (int k = 0; k < KC; k++) wreg[k] = __ldg(&W[lp * KC + k]);

    const int isbyte = g_mask_is_byte;
    const int esz    = isbyte ? 1 : 4;
    const int sliceb = HWRD * esz;                    // 1664 or 416 B
    const int nops   = sliceb >> 4;                   // 104 or 26 cp16 ops per slice
    // source base for this warp's slice of chunk c: edge (c*4+celw), half
    const uint8_t* Msl = M + ((size_t)(e0 + celw) * WPE + (size_t)half * HWRD) * esz;
    const size_t   cstr = (size_t)CHE * WPE * esz;    // chunk stride in bytes
    const uint32_t mb_s = (uint32_t)__cvta_generic_to_shared(mbuf);
    const uint32_t slice_dst0 = mb_s + 0 * STAGE_B + w * SLICE_B;
    const uint32_t slice_dst1 = mb_s + 1 * STAGE_B + w * SLICE_B;

    // ---- prologue: this warp's slices of chunks 0 and 1 ----
    for (int u = lane; u < nops; u += 32)
        cp16_stream(slice_dst0 + u * 16, Msl + (size_t)u * 16, polF);
    cp_commit();                                      // group: chunk 0 slice
    for (int u = lane; u < nops; u += 32)
        cp16_stream(slice_dst1 + u * 16, Msl + cstr + (size_t)u * 16, polF);
    cp_commit();                                      // group: chunk 1 slice

    __syncthreads();   // kers visible for gather

    // ---- gather x once per block (L2-pinned) ----
    {
        const int gel = tid >> 3, gi = tid & 7;
        #pragma unroll
        for (int k = 0; k < KC; k++) {
            int j = kers[gel * KC + k];
            xsf[gel * IK + gi * KC + k] = ld_pin(&g_xt[(size_t)j * FINC + gi], polL);
        }
    }
    __syncthreads();   // xsf published; hereafter warps free-run

    const float SCALE = (float)((2.0 + 2.0 * 2.718281828459045235) /
                                (2.718281828459045235 - 1.0));

    #pragma unroll 1
    for (int c = 0; c < NCH; c++) {
        const int bsel = c & 1;

        // ---- issue this warp's slice of chunk c+1 (chunks 0,1 pre-issued).
        //      Target buffer bsel^1 was consumed by THIS warp at iter c-1. ----
        if (c >= 1 && c + 1 < NCH) {
            const uint8_t* src = Msl + (size_t)(c + 1) * cstr;
            const uint32_t dst = bsel ? slice_dst0 : slice_dst1;
            for (int u = lane; u < nops; u += 32)
                cp16_stream(dst + u * 16, src + (size_t)u * 16, polF);
            cp_commit();
        }
        // outstanding groups: {c, c+1} (or {c} on the last iteration)
        if (c + 1 < NCH) cp_wait<1>();
        else             cp_wait<0>();
        __syncwarp();    // all lanes' copies of slice c visible warp-wide

        // ---- compute chunk c: lane (o-local, ii) does 13 MACs for edge eg ----
        const int eg = c * CHE + celw;
        const float* xrow = &xsf[eg * IK + ii * KC];

        float acc = 0.0f;
        if (!isbyte) {
            const uint32_t* mrow = mbuf + (bsel * STAGE_B + w * SLICE_B) / 4 + lane * KC;
            #pragma unroll
            for (int k = 0; k < KC; k++)
                if (mrow[k]) acc = fmaf(wreg[k], xrow[k], acc);
        } else {
            const uint8_t* mrow = reinterpret_cast<const uint8_t*>(mbuf) +
                                  bsel * STAGE_B + w * SLICE_B + lane * KC;
            #pragma unroll
            for (int k = 0; k < KC; k++)
                if (mrow[k]) acc = fmaf(wreg[k], xrow[k], acc);
        }

        // reduce over input features (lane bits 0..2, in-warp)
        acc += __shfl_xor_sync(0xffffffffu, acc, 1);
        acc += __shfl_xor_sync(0xffffffffu, acc, 2);
        acc += __shfl_xor_sync(0xffffffffu, acc, 4);

        if (ii == 0) {
            float z = acc + bsh[o];
            float s = 1.0f / (1.0f + __expf(-z));
            __stcs(&out[(size_t)o * NC + els[eg]], (s - 0.5f) * SCALE);
        }
        __syncwarp();    // lanes done with slice (buffer reused by this warp at c+1)
    }
}

extern "C" void kernel_launch(void* const* d_in, const int* in_sizes, int n_in,
                              void* d_out, int out_size) {
    const float*   x   = (const float*)  d_in[0];
    const float*   Wh  = (const float*)  d_in[1];
    const float*   Wv  = (const float*)  d_in[2];
    const float*   bh  = (const float*)  d_in[3];
    const float*   bv  = (const float*)  d_in[4];
    const uint8_t* Mh  = (const uint8_t*)d_in[5];
    const uint8_t* Mv  = (const uint8_t*)d_in[6];
    const int*     Kh  = (const int*)    d_in[7];
    const int*     Kv  = (const int*)    d_in[8];
    const int*     ELh = (const int*)    d_in[9];
    const int*     ELv = (const int*)    d_in[10];
    float* out = (float*)d_out;

    prep_kernel<<<NC / TPB, TPB>>>(x, (const uint32_t*)Mh);

    dim3 grid(L2C / EPB, 2);   // y=0 horizontal branch, y=1 vertical
    edge_kernel<<<grid, TPB>>>(Wh, Wv, bh, bv, Mh, Mv, Kh, Kv, ELh, ELv, out);
}